// round 10
// baseline (speedup 1.0000x reference)
#include <cuda_runtime.h>
#include <math.h>
#include <stdint.h>

#define SEQ    2048
#define BATCH  2
#define DIM    1024
#define HEADS  16
#define DH     64
#define MROWS  (BATCH*SEQ)          // 4096
#define QKVCOL (3*DIM)              // 3072

__device__ float g_qkv [MROWS * QKVCOL];   // raw fp32 qkv
__device__ float g_attn[MROWS * DIM];      // raw fp32 attention out
__device__ float g_xc  [MROWS * DIM];      // tf32-rounded x
__device__ float g_wqc [QKVCOL * DIM];     // tf32-rounded W_qkv
__device__ float g_woc [DIM * DIM];        // tf32-rounded W_out
__device__ float g_atc [MROWS * DIM];      // tf32-rounded attn out

// ---------------------------------------------------------------------------
__device__ __forceinline__ uint32_t f2tf(float x){
    uint32_t r; asm("cvt.rna.tf32.f32 %0, %1;" : "=r"(r) : "f"(x)); return r;
}
__device__ __forceinline__ uint32_t smem_u32(const void* p){
    return (uint32_t)__cvta_generic_to_shared(p);
}
__device__ __forceinline__ void mma8(float* c, const uint32_t* a, const uint32_t* b){
    asm volatile("mma.sync.aligned.m16n8k8.row.col.f32.tf32.tf32.f32 "
        "{%0,%1,%2,%3}, {%4,%5,%6,%7}, {%8,%9}, {%0,%1,%2,%3};"
        : "+f"(c[0]),"+f"(c[1]),"+f"(c[2]),"+f"(c[3])
        : "r"(a[0]),"r"(a[1]),"r"(a[2]),"r"(a[3]),"r"(b[0]),"r"(b[1]));
}
__device__ __forceinline__ void ldsm4(uint32_t& r0, uint32_t& r1, uint32_t& r2, uint32_t& r3,
                                      uint32_t addr){
    asm volatile("ldmatrix.sync.aligned.m8n8.x4.shared.b16 {%0,%1,%2,%3}, [%4];"
        : "=r"(r0),"=r"(r1),"=r"(r2),"=r"(r3) : "r"(addr));
}
#define CP16(dst, src) \
    asm volatile("cp.async.cg.shared.global [%0], [%1], 16;" :: "r"(dst), "l"(src))
#define CP_COMMIT() asm volatile("cp.async.commit_group;" ::: "memory")
#define CP_WAIT2()  asm volatile("cp.async.wait_group 2;"  ::: "memory")

// ---------------------------------------------------------------------------
// tf32-RNA pre-convert (fp32 -> fp32-bit-pattern rounded to tf32)
// ---------------------------------------------------------------------------
__global__ void cvt_tf32(const float* __restrict__ in, uint32_t* __restrict__ out, int n4)
{
    int i = blockIdx.x * blockDim.x + threadIdx.x;
    if (i < n4) {
        float4 v = ((const float4*)in)[i];
        ((uint4*)out)[i] = make_uint4(f2tf(v.x), f2tf(v.y), f2tf(v.z), f2tf(v.w));
    }
}

// ---------------------------------------------------------------------------
// tf32 GEMM, cp.async 4-stage pipeline.
// C[M,N] = A[M,K] @ B[N,K]^T, inputs pre-rounded to tf32.
// CTA 128x128, 256 threads (8 warps 4x2), warp tile 32x64, BK=16.
// smem stage: A 128 rows x 80B + B 128 rows x 80B = 20480B; 4 stages = 80KB.
// ---------------------------------------------------------------------------
#define GRB   80u          // row stride bytes (20 words, conflict-free)
#define STGB  20480u       // stage bytes
#define NSTG  4
#define G_SMEM (NSTG*STGB) // 81920

__global__ void __launch_bounds__(256,2) gemm_cp(const float* __restrict__ A,
                                                 const float* __restrict__ B,
                                                 float* __restrict__ C,
                                                 int M, int N, int K)
{
    extern __shared__ __align__(16) unsigned char smem[];
    const uint32_t sb = smem_u32(smem);

    const int tid  = threadIdx.x;
    const int lane = tid & 31, wid = tid >> 5;
    const int g = lane >> 2, t = lane & 3;
    const int wm = wid & 3, wn = wid >> 2;
    const int bm = blockIdx.y * 128, bn = blockIdx.x * 128;

    const uint32_t a_lo = (uint32_t)(((lane & 7) + ((lane >> 3) & 1) * 8) * GRB + (lane >> 4) * 16);
    const uint32_t b_lo = (uint32_t)(((lane & 7) + ((lane >> 4) & 1) * 8) * GRB + ((lane >> 3) & 1) * 16);

    // fill mapping: threads 0..127 own A rows, 128..255 own B rows; 64B per row per stage
    const bool isA = tid < 128;
    const int  r   = isA ? tid : tid - 128;
    const float* gsrc = isA ? (A + (size_t)(bm + r) * K) : (B + (size_t)(bn + r) * K);
    const uint32_t sdst = sb + (isA ? 0u : 10240u) + (uint32_t)r * GRB;

    const int NC = K / 16;

    // prologue: stages 0..2
    #pragma unroll
    for (int s = 0; s < NSTG - 1; s++) {
        const float* src = gsrc + s * 16;
        const uint32_t d = sdst + (uint32_t)s * STGB;
        CP16(d,      src);
        CP16(d + 16, src + 4);
        CP16(d + 32, src + 8);
        CP16(d + 48, src + 12);
        CP_COMMIT();
    }

    float acc[2][8][4] = {};

    for (int c = 0; c < NC; c++) {
        CP_WAIT2();
        __syncthreads();

        // issue stage c+3 (overwrites buffer used at iter c-1; safe after barrier)
        if (c + NSTG - 1 < NC) {
            const float* src = gsrc + (c + NSTG - 1) * 16;
            const uint32_t d = sdst + (uint32_t)((c + NSTG - 1) & (NSTG - 1)) * STGB;
            CP16(d,      src);
            CP16(d + 16, src + 4);
            CP16(d + 32, src + 8);
            CP16(d + 48, src + 12);
        }
        CP_COMMIT();   // commit every iter so wait_group counts stay aligned

        const uint32_t stg   = sb + (uint32_t)(c & (NSTG - 1)) * STGB;
        const uint32_t abase = stg + (uint32_t)(wm * 32) * GRB;
        const uint32_t bbase = stg + 10240u + (uint32_t)(wn * 64) * GRB;

        #pragma unroll
        for (int ks = 0; ks < 2; ks++) {
            uint32_t af[2][4], bf[8][2];
            #pragma unroll
            for (int ma = 0; ma < 2; ma++)
                ldsm4(af[ma][0], af[ma][1], af[ma][2], af[ma][3],
                      abase + (uint32_t)(ma * 16) * GRB + (uint32_t)(ks * 32) + a_lo);
            #pragma unroll
            for (int p = 0; p < 4; p++)
                ldsm4(bf[2*p][0], bf[2*p][1], bf[2*p+1][0], bf[2*p+1][1],
                      bbase + (uint32_t)(p * 16) * GRB + (uint32_t)(ks * 32) + b_lo);
            #pragma unroll
            for (int ma = 0; ma < 2; ma++)
                #pragma unroll
                for (int nb = 0; nb < 8; nb++)
                    mma8(acc[ma][nb], af[ma], bf[nb]);
        }
        __syncthreads();
    }

    #pragma unroll
    for (int ma = 0; ma < 2; ma++) {
        const int r0 = bm + wm*32 + ma*16 + g;
        #pragma unroll
        for (int nb = 0; nb < 8; nb++) {
            const int c0 = bn + wn*64 + nb*8 + 2*t;
            *(float2*)&C[(size_t)r0     * N + c0] = make_float2(acc[ma][nb][0], acc[ma][nb][1]);
            *(float2*)&C[(size_t)(r0+8) * N + c0] = make_float2(acc[ma][nb][2], acc[ma][nb][3]);
        }
    }
}

// ---------------------------------------------------------------------------
// Flash attention, tf32 mma.sync + ldmatrix, register-prefetched KV tiles.
// (Round-8 version, verbatim.)
// ---------------------------------------------------------------------------
#define KST 68

__global__ void __launch_bounds__(256) attn_tf32(const float* __restrict__ qkv,
                                                 float* __restrict__ outp)
{
    __shared__ uint32_t sh[2*64*KST];
    float*    Qs = (float*)sh;
    uint32_t* Ks = sh;                          // [64 kv][KST]
    uint32_t* Vt = sh + 64*KST;                 // [64 dh][KST] (transposed)

    const int tid = threadIdx.x;
    const int lane = tid & 31, wid = tid >> 5;
    const int g = lane >> 2, t = lane & 3;
    const int bh = blockIdx.y, b = bh >> 4, h = bh & 15;
    const int q0 = blockIdx.x * 128;
    const float* base = qkv + (size_t)b * SEQ * QKVCOL;

    const uint32_t Ks0 = smem_u32(Ks), Vt0 = smem_u32(Vt);
    const uint32_t f_lo = ((((lane & 7) + ((lane >> 4) & 1) * 8) * KST) + ((lane >> 3) & 1) * 4) * 4;

    {
        const int r = tid >> 1, f0 = (tid & 1) * 32;
        const float* qr = base + (size_t)(q0 + r) * QKVCOL + h*DH + f0;
        float* dst = Qs + r*KST + f0;
        #pragma unroll
        for (int i = 0; i < 8; i++) ((float4*)dst)[i] = ((const float4*)qr)[i];
    }
    __syncthreads();

    uint32_t qf[8][4];
    {
        const float* qb = Qs + (wid*16 + g) * KST;
        #pragma unroll
        for (int kk = 0; kk < 8; kk++) {
            qf[kk][0] = f2tf(qb[kk*8 + t]             * 0.125f);
            qf[kk][1] = f2tf(qb[8*KST + kk*8 + t]     * 0.125f);
            qf[kk][2] = f2tf(qb[kk*8 + t + 4]         * 0.125f);
            qf[kk][3] = f2tf(qb[8*KST + kk*8 + t + 4] * 0.125f);
        }
    }
    __syncthreads();

    float o[8][4] = {};
    float m0 = -INFINITY, m1 = -INFINITY, l0 = 0.f, l1 = 0.f;
    const int row0 = q0 + wid*16 + g;
    const int ntiles = q0/64 + 2;

    const int fr = tid & 63, fc = (tid >> 6) * 16;
    const float* Kg = base + (size_t)fr * QKVCOL +     DIM + h*DH + fc;
    const float* Vg = base + (size_t)fr * QKVCOL + 2 * DIM + h*DH + fc;
    const size_t tstep = (size_t)64 * QKVCOL;

    float4 rk[4], rv[4];
    #pragma unroll
    for (int i = 0; i < 4; i++) { rk[i] = ((const float4*)Kg)[i]; rv[i] = ((const float4*)Vg)[i]; }

    for (int kt = 0; kt < ntiles; kt++) {
        {
            uint32_t* kd = Ks + fr*KST + fc;
            #pragma unroll
            for (int i = 0; i < 4; i++) {
                ((uint4*)kd)[i] = make_uint4(f2tf(rk[i].x),f2tf(rk[i].y),f2tf(rk[i].z),f2tf(rk[i].w));
                Vt[(fc + 4*i    )*KST + fr] = f2tf(rv[i].x);
                Vt[(fc + 4*i + 1)*KST + fr] = f2tf(rv[i].y);
                Vt[(fc + 4*i + 2)*KST + fr] = f2tf(rv[i].z);
                Vt[(fc + 4*i + 3)*KST + fr] = f2tf(rv[i].w);
            }
        }
        __syncthreads();

        if (kt + 1 < ntiles) {
            const float* Kg2 = Kg + (size_t)(kt + 1) * tstep;
            const float* Vg2 = Vg + (size_t)(kt + 1) * tstep;
            #pragma unroll
            for (int i = 0; i < 4; i++) { rk[i] = ((const float4*)Kg2)[i]; rv[i] = ((const float4*)Vg2)[i]; }
        }

        float s[8][4] = {};
        #pragma unroll
        for (int kk = 0; kk < 8; kk++) {
            uint32_t bk[8][2];
            #pragma unroll
            for (int p = 0; p < 4; p++)
                ldsm4(bk[2*p][0], bk[2*p][1], bk[2*p+1][0], bk[2*p+1][1],
                      Ks0 + (uint32_t)(p * 16 * KST + kk * 8) * 4 + f_lo);
            #pragma unroll
            for (int nb = 0; nb < 8; nb++)
                mma8(s[nb], qf[kk], bk[nb]);
        }

        const int colbase = kt*64 + 2*t;
        float t0 = -INFINITY, t1 = -INFINITY;
        #pragma unroll
        for (int na = 0; na < 8; na++) {
            const int c = colbase + na*8;
            if (c     > row0)     s[na][0] = -INFINITY;
            if (c + 1 > row0)     s[na][1] = -INFINITY;
            if (c     > row0 + 8) s[na][2] = -INFINITY;
            if (c + 1 > row0 + 8) s[na][3] = -INFINITY;
            t0 = fmaxf(t0, fmaxf(s[na][0], s[na][1]));
            t1 = fmaxf(t1, fmaxf(s[na][2], s[na][3]));
        }
        t0 = fmaxf(t0, __shfl_xor_sync(0xffffffffu, t0, 1));
        t0 = fmaxf(t0, __shfl_xor_sync(0xffffffffu, t0, 2));
        t1 = fmaxf(t1, __shfl_xor_sync(0xffffffffu, t1, 1));
        t1 = fmaxf(t1, __shfl_xor_sync(0xffffffffu, t1, 2));

        const float mn0 = fmaxf(m0, t0), mn1 = fmaxf(m1, t1);
        const float sc0 = __expf(m0 - mn0), sc1 = __expf(m1 - mn1);
        m0 = mn0; m1 = mn1; l0 *= sc0; l1 *= sc1;

        #pragma unroll
        for (int na = 0; na < 8; na++) {
            o[na][0] *= sc0; o[na][1] *= sc0; o[na][2] *= sc1; o[na][3] *= sc1;
            s[na][0] = __expf(s[na][0] - m0);
            s[na][1] = __expf(s[na][1] - m0);
            s[na][2] = __expf(s[na][2] - m1);
            s[na][3] = __expf(s[na][3] - m1);
            l0 += s[na][0] + s[na][1];
            l1 += s[na][2] + s[na][3];
        }

        #pragma unroll
        for (int kk = 0; kk < 8; kk++) {
            const int srcA = (lane & ~3) | (t >> 1);
            const int srcB = srcA + 2;
            float y0 = __shfl_sync(0xffffffffu, s[kk][0], srcA);
            float y1 = __shfl_sync(0xffffffffu, s[kk][1], srcA);
            float y2 = __shfl_sync(0xffffffffu, s[kk][2], srcA);
            float y3 = __shfl_sync(0xffffffffu, s[kk][3], srcA);
            float z0 = __shfl_sync(0xffffffffu, s[kk][0], srcB);
            float z1 = __shfl_sync(0xffffffffu, s[kk][1], srcB);
            float z2 = __shfl_sync(0xffffffffu, s[kk][2], srcB);
            float z3 = __shfl_sync(0xffffffffu, s[kk][3], srcB);
            uint32_t pa[4];
            pa[0] = f2tf((t & 1) ? y1 : y0);
            pa[1] = f2tf((t & 1) ? y3 : y2);
            pa[2] = f2tf((t & 1) ? z1 : z0);
            pa[3] = f2tf((t & 1) ? z3 : z2);

            uint32_t bv[8][2];
            #pragma unroll
            for (int p = 0; p < 4; p++)
                ldsm4(bv[2*p][0], bv[2*p][1], bv[2*p+1][0], bv[2*p+1][1],
                      Vt0 + (uint32_t)(p * 16 * KST + kk * 8) * 4 + f_lo);
            #pragma unroll
            for (int na = 0; na < 8; na++)
                mma8(o[na], pa, bv[na]);
        }
        __syncthreads();
    }

    l0 += __shfl_xor_sync(0xffffffffu, l0, 1);
    l0 += __shfl_xor_sync(0xffffffffu, l0, 2);
    l1 += __shfl_xor_sync(0xffffffffu, l1, 1);
    l1 += __shfl_xor_sync(0xffffffffu, l1, 2);
    const float i0 = 1.f / l0, i1 = 1.f / l1;

    float* orow0 = outp + (size_t)(b*SEQ + row0) * DIM + h*DH;
    float* orow1 = orow0 + 8*DIM;
    #pragma unroll
    for (int na = 0; na < 8; na++) {
        *(float2*)&orow0[na*8 + 2*t] = make_float2(o[na][0]*i0, o[na][1]*i0);
        *(float2*)&orow1[na*8 + 2*t] = make_float2(o[na][2]*i1, o[na][3]*i1);
    }
}

// ---------------------------------------------------------------------------
extern "C" void kernel_launch(void* const* d_in, const int* in_sizes, int n_in,
                              void* d_out, int out_size)
{
    const float* x     = (const float*)d_in[0];
    const float* W_qkv = (const float*)d_in[1];
    const float* W_out = (const float*)d_in[2];
    float*       out   = (float*)d_out;

    float *qkv, *attn, *xc, *wqc, *woc, *atc;
    cudaGetSymbolAddress((void**)&qkv,  g_qkv);
    cudaGetSymbolAddress((void**)&attn, g_attn);
    cudaGetSymbolAddress((void**)&xc,   g_xc);
    cudaGetSymbolAddress((void**)&wqc,  g_wqc);
    cudaGetSymbolAddress((void**)&woc,  g_woc);
    cudaGetSymbolAddress((void**)&atc,  g_atc);

    cudaFuncSetAttribute(gemm_cp, cudaFuncAttributeMaxDynamicSharedMemorySize, G_SMEM);

    // pre-round weights/activations to tf32 (RNA)
    cvt_tf32<<<(MROWS*DIM/4 + 255)/256, 256>>>(x,     (uint32_t*)xc,  MROWS*DIM/4);
    cvt_tf32<<<(QKVCOL*DIM/4 + 255)/256, 256>>>(W_qkv,(uint32_t*)wqc, QKVCOL*DIM/4);
    cvt_tf32<<<(DIM*DIM/4 + 255)/256, 256>>>(W_out,  (uint32_t*)woc, DIM*DIM/4);

    // 1) qkv = x @ W_qkv^T
    gemm_cp<<<dim3(QKVCOL/128, MROWS/128), 256, G_SMEM>>>(xc, wqc, qkv, MROWS, QKVCOL, DIM);
    // 2) causal attention
    attn_tf32<<<dim3(SEQ/128, BATCH*HEADS), 256>>>(qkv, attn);
    // 2b) round attention output
    cvt_tf32<<<(MROWS*DIM/4 + 255)/256, 256>>>(attn, (uint32_t*)atc, MROWS*DIM/4);
    // 3) out = attn @ W_out^T
    gemm_cp<<<dim3(DIM/128, MROWS/128), 256, G_SMEM>>>(atc, woc, out, MROWS, DIM, DIM);
}

// round 11
// speedup vs baseline: 2.2520x; 2.2520x over previous
#include <cuda_runtime.h>
#include <cuda_fp16.h>
#include <math.h>
#include <stdint.h>

#define SEQ    2048
#define BATCH  2
#define DIM    1024
#define HEADS  16
#define DH     64
#define MROWS  (BATCH*SEQ)          // 4096
#define QKVCOL (3*DIM)              // 3072

__device__ float g_qkv [MROWS * QKVCOL];
__device__ float g_attn[MROWS * DIM];

// ---------------------------------------------------------------------------
__device__ __forceinline__ uint32_t smem_u32(const void* p){
    return (uint32_t)__cvta_generic_to_shared(p);
}
__device__ __forceinline__ uint32_t pkh(float lo, float hi){
    __half2 h = __floats2half2_rn(lo, hi);
    return *reinterpret_cast<uint32_t*>(&h);
}
__device__ __forceinline__ void mma16(float* c, const uint32_t* a, const uint32_t* b){
    asm volatile("mma.sync.aligned.m16n8k16.row.col.f32.f16.f16.f32 "
        "{%0,%1,%2,%3}, {%4,%5,%6,%7}, {%8,%9}, {%0,%1,%2,%3};"
        : "+f"(c[0]),"+f"(c[1]),"+f"(c[2]),"+f"(c[3])
        : "r"(a[0]),"r"(a[1]),"r"(a[2]),"r"(a[3]),"r"(b[0]),"r"(b[1]));
}
__device__ __forceinline__ void ldsm4(uint32_t& r0, uint32_t& r1, uint32_t& r2, uint32_t& r3,
                                      uint32_t addr){
    asm volatile("ldmatrix.sync.aligned.m8n8.x4.shared.b16 {%0,%1,%2,%3}, [%4];"
        : "=r"(r0),"=r"(r1),"=r"(r2),"=r"(r3) : "r"(addr));
}
__device__ __forceinline__ void ldsm4t(uint32_t& r0, uint32_t& r1, uint32_t& r2, uint32_t& r3,
                                       uint32_t addr){
    asm volatile("ldmatrix.sync.aligned.m8n8.x4.trans.shared.b16 {%0,%1,%2,%3}, [%4];"
        : "=r"(r0),"=r"(r1),"=r"(r2),"=r"(r3) : "r"(addr));
}

// ---------------------------------------------------------------------------
// fp16 GEMM, Round-8 skeleton: C[M,N] = A[M,K] @ B[N,K]^T.
// CTA 128x128, 256 threads (8 warps 4x2), warp tile 32x64, BK=16,
// double-buffered fp16 smem (row stride 48B = odd*16 -> conflict-free ldsm).
// ---------------------------------------------------------------------------
#define S48  48u
#define HBUF (128*S48)   // 6144 B per matrix per stage

__global__ void __launch_bounds__(256,2) gemm_h(const float* __restrict__ A,
                                                const float* __restrict__ B,
                                                float* __restrict__ C,
                                                int M, int N, int K)
{
    __shared__ __align__(16) unsigned char As[2][HBUF];
    __shared__ __align__(16) unsigned char Bs[2][HBUF];

    const int tid  = threadIdx.x;
    const int lane = tid & 31, wid = tid >> 5;
    const int g = lane >> 2, t = lane & 3;
    const int wm = wid & 3, wn = wid >> 2;
    const int bm = blockIdx.y * 128, bn = blockIdx.x * 128;

    const uint32_t As0 = smem_u32(As), Bs0 = smem_u32(Bs);
    const uint32_t a_lo = (uint32_t)((lane & 15) * S48 + (lane >> 4) * 16);
    const uint32_t b_lo = (uint32_t)(((lane & 7) + ((lane >> 4) & 1) * 8) * S48 + ((lane >> 3) & 1) * 16);

    // fill: thread owns row tid>>1, 8 k-floats at offset (tid&1)*8 -> 16B fp16
    const int frow = tid >> 1, fko = (tid & 1) * 8;
    const float* Ag = A + (size_t)(bm + frow) * K + fko;
    const float* Bg = B + (size_t)(bn + frow) * K + fko;
    const uint32_t sA = As0 + (uint32_t)(frow * S48 + (tid & 1) * 16);
    const uint32_t sB = Bs0 + (uint32_t)(frow * S48 + (tid & 1) * 16);

    float acc[2][8][4] = {};
    const int NC = K / 16;

    float4 ra[2], rb[2];
    #pragma unroll
    for (int i = 0; i < 2; i++) { ra[i] = ((const float4*)Ag)[i]; rb[i] = ((const float4*)Bg)[i]; }
    asm volatile("st.shared.v4.b32 [%0], {%1,%2,%3,%4};" :: "r"(sA),
        "r"(pkh(ra[0].x,ra[0].y)), "r"(pkh(ra[0].z,ra[0].w)),
        "r"(pkh(ra[1].x,ra[1].y)), "r"(pkh(ra[1].z,ra[1].w)));
    asm volatile("st.shared.v4.b32 [%0], {%1,%2,%3,%4};" :: "r"(sB),
        "r"(pkh(rb[0].x,rb[0].y)), "r"(pkh(rb[0].z,rb[0].w)),
        "r"(pkh(rb[1].x,rb[1].y)), "r"(pkh(rb[1].z,rb[1].w)));
    __syncthreads();

    for (int c = 0; c < NC; c++) {
        const int buf = c & 1;
        const uint32_t abase = As0 + (uint32_t)buf * HBUF + (uint32_t)(wm * 32) * S48;
        const uint32_t bbase = Bs0 + (uint32_t)buf * HBUF + (uint32_t)(wn * 64) * S48;

        if (c + 1 < NC) {
            const float* Ag2 = Ag + (c + 1) * 16;
            const float* Bg2 = Bg + (c + 1) * 16;
            #pragma unroll
            for (int i = 0; i < 2; i++) { ra[i] = ((const float4*)Ag2)[i]; rb[i] = ((const float4*)Bg2)[i]; }
        }

        uint32_t af[2][4], bf[8][2];
        #pragma unroll
        for (int ma = 0; ma < 2; ma++)
            ldsm4(af[ma][0], af[ma][1], af[ma][2], af[ma][3],
                  abase + (uint32_t)(ma * 16) * S48 + a_lo);
        #pragma unroll
        for (int p = 0; p < 4; p++)
            ldsm4(bf[2*p][0], bf[2*p][1], bf[2*p+1][0], bf[2*p+1][1],
                  bbase + (uint32_t)(p * 16) * S48 + b_lo);
        #pragma unroll
        for (int ma = 0; ma < 2; ma++)
            #pragma unroll
            for (int nb = 0; nb < 8; nb++)
                mma16(acc[ma][nb], af[ma], bf[nb]);

        if (c + 1 < NC) {
            const uint32_t dA = sA + (uint32_t)((buf ^ 1)) * HBUF;
            const uint32_t dB = sB + (uint32_t)((buf ^ 1)) * HBUF;
            asm volatile("st.shared.v4.b32 [%0], {%1,%2,%3,%4};" :: "r"(dA),
                "r"(pkh(ra[0].x,ra[0].y)), "r"(pkh(ra[0].z,ra[0].w)),
                "r"(pkh(ra[1].x,ra[1].y)), "r"(pkh(ra[1].z,ra[1].w)));
            asm volatile("st.shared.v4.b32 [%0], {%1,%2,%3,%4};" :: "r"(dB),
                "r"(pkh(rb[0].x,rb[0].y)), "r"(pkh(rb[0].z,rb[0].w)),
                "r"(pkh(rb[1].x,rb[1].y)), "r"(pkh(rb[1].z,rb[1].w)));
        }
        __syncthreads();
    }

    #pragma unroll
    for (int ma = 0; ma < 2; ma++) {
        const int r0 = bm + wm*32 + ma*16 + g;
        #pragma unroll
        for (int nb = 0; nb < 8; nb++) {
            const int c0 = bn + wn*64 + nb*8 + 2*t;
            *(float2*)&C[(size_t)r0     * N + c0] = make_float2(acc[ma][nb][0], acc[ma][nb][1]);
            *(float2*)&C[(size_t)(r0+8) * N + c0] = make_float2(acc[ma][nb][2], acc[ma][nb][3]);
        }
    }
}

// ---------------------------------------------------------------------------
// Flash attention, fp16 mma.sync m16n8k16 (Round-9 version, verified correct).
// P packs directly into fp16 a-frags; V fragments via ldmatrix.trans.
// ---------------------------------------------------------------------------
#define ARB 144         // row stride bytes (72 fp16; 144/16=9 odd -> conflict-free)

__global__ void __launch_bounds__(256) attn_h(const float* __restrict__ qkv,
                                              float* __restrict__ outp)
{
    __shared__ __align__(16) __half sh[2*64*72];
    __half* Ks = sh;                                // [64 kv][72]
    __half* Vs = sh + 64*72;                        // [64 kv][72]
    __half* Qs = sh;                                // [128 q][72] staging overlay

    const int tid = threadIdx.x;
    const int lane = tid & 31, wid = tid >> 5;
    const int g = lane >> 2, t = lane & 3;
    const int bh = blockIdx.y, b = bh >> 4, h = bh & 15;
    const int q0 = blockIdx.x * 128;
    const float* base = qkv + (size_t)b * SEQ * QKVCOL;

    const uint32_t Ks0 = smem_u32(Ks), Vs0 = smem_u32(Vs), Qs0 = smem_u32(Qs);
    const uint32_t a_lo = (uint32_t)((lane & 15) * ARB + (lane >> 4) * 16);
    const uint32_t b_lo = (uint32_t)(((lane & 7) + ((lane >> 4) & 1) * 8) * ARB + ((lane >> 3) & 1) * 16);
    const uint32_t v_lo = (uint32_t)(((lane & 7) + ((lane >> 3) & 1) * 8) * ARB + (lane >> 4) * 16);

    // stage Q (scaled by 1/8, fp16)
    {
        const int r = tid >> 1, f0 = (tid & 1) * 32;
        const float* qr = base + (size_t)(q0 + r) * QKVCOL + h*DH + f0;
        uint32_t dst = Qs0 + (uint32_t)(r * ARB + f0 * 2);
        #pragma unroll
        for (int i = 0; i < 4; i++) {
            float4 q0v = ((const float4*)qr)[2*i];
            float4 q1v = ((const float4*)qr)[2*i+1];
            asm volatile("st.shared.v4.b32 [%0], {%1,%2,%3,%4};" :: "r"(dst + i*16),
                "r"(pkh(q0v.x*0.125f,q0v.y*0.125f)), "r"(pkh(q0v.z*0.125f,q0v.w*0.125f)),
                "r"(pkh(q1v.x*0.125f,q1v.y*0.125f)), "r"(pkh(q1v.z*0.125f,q1v.w*0.125f)));
        }
    }
    __syncthreads();

    uint32_t qf[4][4];
    #pragma unroll
    for (int kc = 0; kc < 4; kc++)
        ldsm4(qf[kc][0], qf[kc][1], qf[kc][2], qf[kc][3],
              Qs0 + (uint32_t)(wid * 16 * ARB + kc * 32) + a_lo);
    __syncthreads();

    float o[8][4] = {};
    float m0 = -INFINITY, m1 = -INFINITY, l0 = 0.f, l1 = 0.f;
    const int row0 = q0 + wid*16 + g;
    const int ntiles = q0/64 + 2;

    const int fr = tid & 63, fc = (tid >> 6) * 16;
    const float* Kg = base + (size_t)fr * QKVCOL +     DIM + h*DH + fc;
    const float* Vg = base + (size_t)fr * QKVCOL + 2 * DIM + h*DH + fc;
    const size_t tstep = (size_t)64 * QKVCOL;
    const uint32_t kdst = Ks0 + (uint32_t)(fr * ARB + fc * 2);
    const uint32_t vdst = Vs0 + (uint32_t)(fr * ARB + fc * 2);

    float4 rk[4], rv[4];
    #pragma unroll
    for (int i = 0; i < 4; i++) { rk[i] = ((const float4*)Kg)[i]; rv[i] = ((const float4*)Vg)[i]; }

    for (int kt = 0; kt < ntiles; kt++) {
        #pragma unroll
        for (int i = 0; i < 2; i++) {
            asm volatile("st.shared.v4.b32 [%0], {%1,%2,%3,%4};" :: "r"(kdst + i*16),
                "r"(pkh(rk[2*i].x,rk[2*i].y)), "r"(pkh(rk[2*i].z,rk[2*i].w)),
                "r"(pkh(rk[2*i+1].x,rk[2*i+1].y)), "r"(pkh(rk[2*i+1].z,rk[2*i+1].w)));
            asm volatile("st.shared.v4.b32 [%0], {%1,%2,%3,%4};" :: "r"(vdst + i*16),
                "r"(pkh(rv[2*i].x,rv[2*i].y)), "r"(pkh(rv[2*i].z,rv[2*i].w)),
                "r"(pkh(rv[2*i+1].x,rv[2*i+1].y)), "r"(pkh(rv[2*i+1].z,rv[2*i+1].w)));
        }
        __syncthreads();

        if (kt + 1 < ntiles) {
            const float* Kg2 = Kg + (size_t)(kt + 1) * tstep;
            const float* Vg2 = Vg + (size_t)(kt + 1) * tstep;
            #pragma unroll
            for (int i = 0; i < 4; i++) { rk[i] = ((const float4*)Kg2)[i]; rv[i] = ((const float4*)Vg2)[i]; }
        }

        // ---- S = Q @ K^T ----
        float s[8][4] = {};
        #pragma unroll
        for (int kc = 0; kc < 4; kc++) {
            uint32_t bk[8][2];
            #pragma unroll
            for (int p = 0; p < 4; p++)
                ldsm4(bk[2*p][0], bk[2*p][1], bk[2*p+1][0], bk[2*p+1][1],
                      Ks0 + (uint32_t)(p * 16 * ARB + kc * 32) + b_lo);
            #pragma unroll
            for (int nb = 0; nb < 8; nb++)
                mma16(s[nb], qf[kc], bk[nb]);
        }

        // ---- causal mask + online softmax ----
        const int colbase = kt*64 + 2*t;
        float t0 = -INFINITY, t1 = -INFINITY;
        #pragma unroll
        for (int na = 0; na < 8; na++) {
            const int c = colbase + na*8;
            if (c     > row0)     s[na][0] = -INFINITY;
            if (c + 1 > row0)     s[na][1] = -INFINITY;
            if (c     > row0 + 8) s[na][2] = -INFINITY;
            if (c + 1 > row0 + 8) s[na][3] = -INFINITY;
            t0 = fmaxf(t0, fmaxf(s[na][0], s[na][1]));
            t1 = fmaxf(t1, fmaxf(s[na][2], s[na][3]));
        }
        t0 = fmaxf(t0, __shfl_xor_sync(0xffffffffu, t0, 1));
        t0 = fmaxf(t0, __shfl_xor_sync(0xffffffffu, t0, 2));
        t1 = fmaxf(t1, __shfl_xor_sync(0xffffffffu, t1, 1));
        t1 = fmaxf(t1, __shfl_xor_sync(0xffffffffu, t1, 2));

        const float mn0 = fmaxf(m0, t0), mn1 = fmaxf(m1, t1);
        const float sc0 = __expf(m0 - mn0), sc1 = __expf(m1 - mn1);
        m0 = mn0; m1 = mn1; l0 *= sc0; l1 *= sc1;

        #pragma unroll
        for (int na = 0; na < 8; na++) {
            o[na][0] *= sc0; o[na][1] *= sc0; o[na][2] *= sc1; o[na][3] *= sc1;
            s[na][0] = __expf(s[na][0] - m0);
            s[na][1] = __expf(s[na][1] - m0);
            s[na][2] = __expf(s[na][2] - m1);
            s[na][3] = __expf(s[na][3] - m1);
            l0 += s[na][0] + s[na][1];
            l1 += s[na][2] + s[na][3];
        }

        // ---- O += P @ V ----
        #pragma unroll
        for (int kc = 0; kc < 4; kc++) {
            uint32_t pa[4];
            pa[0] = pkh(s[2*kc][0],   s[2*kc][1]);
            pa[1] = pkh(s[2*kc][2],   s[2*kc][3]);
            pa[2] = pkh(s[2*kc+1][0], s[2*kc+1][1]);
            pa[3] = pkh(s[2*kc+1][2], s[2*kc+1][3]);

            uint32_t bv[8][2];
            #pragma unroll
            for (int p = 0; p < 4; p++)
                ldsm4t(bv[2*p][0], bv[2*p][1], bv[2*p+1][0], bv[2*p+1][1],
                       Vs0 + (uint32_t)(kc * 16 * ARB + p * 32) + v_lo);
            #pragma unroll
            for (int nb = 0; nb < 8; nb++)
                mma16(o[nb], pa, bv[nb]);
        }
        __syncthreads();
    }

    l0 += __shfl_xor_sync(0xffffffffu, l0, 1);
    l0 += __shfl_xor_sync(0xffffffffu, l0, 2);
    l1 += __shfl_xor_sync(0xffffffffu, l1, 1);
    l1 += __shfl_xor_sync(0xffffffffu, l1, 2);
    const float i0 = 1.f / l0, i1 = 1.f / l1;

    float* orow0 = outp + (size_t)(b*SEQ + row0) * DIM + h*DH;
    float* orow1 = orow0 + 8*DIM;
    #pragma unroll
    for (int na = 0; na < 8; na++) {
        *(float2*)&orow0[na*8 + 2*t] = make_float2(o[na][0]*i0, o[na][1]*i0);
        *(float2*)&orow1[na*8 + 2*t] = make_float2(o[na][2]*i1, o[na][3]*i1);
    }
}

// ---------------------------------------------------------------------------
extern "C" void kernel_launch(void* const* d_in, const int* in_sizes, int n_in,
                              void* d_out, int out_size)
{
    const float* x     = (const float*)d_in[0];
    const float* W_qkv = (const float*)d_in[1];
    const float* W_out = (const float*)d_in[2];
    float*       out   = (float*)d_out;

    float *qkv, *attn;
    cudaGetSymbolAddress((void**)&qkv,  g_qkv);
    cudaGetSymbolAddress((void**)&attn, g_attn);

    // 1) qkv = x @ W_qkv^T
    gemm_h<<<dim3(QKVCOL/128, MROWS/128), 256>>>(x, W_qkv, qkv, MROWS, QKVCOL, DIM);
    // 2) causal attention
    attn_h<<<dim3(SEQ/128, BATCH*HEADS), 256>>>(qkv, attn);
    // 3) out = attn @ W_out^T
    gemm_h<<<dim3(DIM/128, MROWS/128), 256>>>(attn, W_out, out, MROWS, DIM, DIM);
}

// round 14
// speedup vs baseline: 2.2786x; 1.0118x over previous
#include <cuda_runtime.h>
#include <cuda_fp16.h>
#include <math.h>
#include <stdint.h>

#define SEQ    2048
#define BATCH  2
#define DIM    1024
#define HEADS  16
#define DH     64
#define MROWS  (BATCH*SEQ)          // 4096
#define QKVCOL (3*DIM)              // 3072

__device__ float g_qkv [MROWS * QKVCOL];
__device__ float g_attn[MROWS * DIM];

// ---------------------------------------------------------------------------
__device__ __forceinline__ uint32_t smem_u32(const void* p){
    return (uint32_t)__cvta_generic_to_shared(p);
}
__device__ __forceinline__ uint32_t pkh(float lo, float hi){
    __half2 h = __floats2half2_rn(lo, hi);
    return *reinterpret_cast<uint32_t*>(&h);
}
__device__ __forceinline__ void mma16(float* c, const uint32_t* a, const uint32_t* b){
    asm volatile("mma.sync.aligned.m16n8k16.row.col.f32.f16.f16.f32 "
        "{%0,%1,%2,%3}, {%4,%5,%6,%7}, {%8,%9}, {%0,%1,%2,%3};"
        : "+f"(c[0]),"+f"(c[1]),"+f"(c[2]),"+f"(c[3])
        : "r"(a[0]),"r"(a[1]),"r"(a[2]),"r"(a[3]),"r"(b[0]),"r"(b[1]));
}
__device__ __forceinline__ void ldsm4(uint32_t& r0, uint32_t& r1, uint32_t& r2, uint32_t& r3,
                                      uint32_t addr){
    asm volatile("ldmatrix.sync.aligned.m8n8.x4.shared.b16 {%0,%1,%2,%3}, [%4];"
        : "=r"(r0),"=r"(r1),"=r"(r2),"=r"(r3) : "r"(addr));
}
__device__ __forceinline__ void ldsm4t(uint32_t& r0, uint32_t& r1, uint32_t& r2, uint32_t& r3,
                                       uint32_t addr){
    asm volatile("ldmatrix.sync.aligned.m8n8.x4.trans.shared.b16 {%0,%1,%2,%3}, [%4];"
        : "=r"(r0),"=r"(r1),"=r"(r2),"=r"(r3) : "r"(addr));
}

// ---------------------------------------------------------------------------
// fp16 GEMM with 3-stage smem pipeline (LDG scheduled 2 chunks ahead).
// C[M,N] = A[M,K] @ B[N,K]^T. CTA 128x128, 256 threads (8 warps 4x2),
// warp tile 32x64, BK=16, fp16 smem rows of 48B (conflict-free ldsm).
// ---------------------------------------------------------------------------
#define S48  48u
#define HBUF (128*S48)   // 6144 B per matrix per stage

__global__ void __launch_bounds__(256,2) gemm_h(const float* __restrict__ A,
                                                const float* __restrict__ B,
                                                float* __restrict__ C,
                                                int M, int N, int K)
{
    __shared__ __align__(16) unsigned char As[3][HBUF];
    __shared__ __align__(16) unsigned char Bs[3][HBUF];

    const int tid  = threadIdx.x;
    const int lane = tid & 31, wid = tid >> 5;
    const int g = lane >> 2, t = lane & 3;
    const int wm = wid & 3, wn = wid >> 2;
    const int bm = blockIdx.y * 128, bn = blockIdx.x * 128;

    const uint32_t As0 = smem_u32(As), Bs0 = smem_u32(Bs);
    const uint32_t a_lo = (uint32_t)((lane & 15) * S48 + (lane >> 4) * 16);
    const uint32_t b_lo = (uint32_t)(((lane & 7) + ((lane >> 4) & 1) * 8) * S48 + ((lane >> 3) & 1) * 16);

    // fill: thread owns row tid>>1, 8 k-floats at offset (tid&1)*8 -> 16B fp16
    const int frow = tid >> 1;
    const float* Ag = A + (size_t)(bm + frow) * K + (tid & 1) * 8;
    const float* Bg = B + (size_t)(bn + frow) * K + (tid & 1) * 8;
    const uint32_t sA = As0 + (uint32_t)(frow * S48 + (tid & 1) * 16);
    const uint32_t sB = Bs0 + (uint32_t)(frow * S48 + (tid & 1) * 16);

    float acc[2][8][4] = {};
    const int NC = K / 16;

    // prologue: chunk 0 -> buf 0 (via regs), chunk 1 -> regs
    float4 ra[2], rb[2];
    #pragma unroll
    for (int i = 0; i < 2; i++) { ra[i] = ((const float4*)Ag)[i]; rb[i] = ((const float4*)Bg)[i]; }
    asm volatile("st.shared.v4.b32 [%0], {%1,%2,%3,%4};" :: "r"(sA),
        "r"(pkh(ra[0].x,ra[0].y)), "r"(pkh(ra[0].z,ra[0].w)),
        "r"(pkh(ra[1].x,ra[1].y)), "r"(pkh(ra[1].z,ra[1].w)));
    asm volatile("st.shared.v4.b32 [%0], {%1,%2,%3,%4};" :: "r"(sB),
        "r"(pkh(rb[0].x,rb[0].y)), "r"(pkh(rb[0].z,rb[0].w)),
        "r"(pkh(rb[1].x,rb[1].y)), "r"(pkh(rb[1].z,rb[1].w)));
    #pragma unroll
    for (int i = 0; i < 2; i++) { ra[i] = ((const float4*)(Ag + 16))[i]; rb[i] = ((const float4*)(Bg + 16))[i]; }
    __syncthreads();

    int bufw = 1;   // buffer receiving the regs' chunk (c+1)
    for (int c = 0; c < NC; c++) {
        // STS chunk c+1 from regs into buf (c+1)%3
        if (c + 1 < NC) {
            const uint32_t dA = sA + (uint32_t)bufw * HBUF;
            const uint32_t dB = sB + (uint32_t)bufw * HBUF;
            asm volatile("st.shared.v4.b32 [%0], {%1,%2,%3,%4};" :: "r"(dA),
                "r"(pkh(ra[0].x,ra[0].y)), "r"(pkh(ra[0].z,ra[0].w)),
                "r"(pkh(ra[1].x,ra[1].y)), "r"(pkh(ra[1].z,ra[1].w)));
            asm volatile("st.shared.v4.b32 [%0], {%1,%2,%3,%4};" :: "r"(dB),
                "r"(pkh(rb[0].x,rb[0].y)), "r"(pkh(rb[0].z,rb[0].w)),
                "r"(pkh(rb[1].x,rb[1].y)), "r"(pkh(rb[1].z,rb[1].w)));
        }
        // LDG chunk c+2 into regs (has ~1.5 iterations to land)
        if (c + 2 < NC) {
            const float* Ag2 = Ag + (c + 2) * 16;
            const float* Bg2 = Bg + (c + 2) * 16;
            #pragma unroll
            for (int i = 0; i < 2; i++) { ra[i] = ((const float4*)Ag2)[i]; rb[i] = ((const float4*)Bg2)[i]; }
        }

        // compute on buf c%3
        const int bufr = (bufw + 2) % 3;
        const uint32_t abase = As0 + (uint32_t)bufr * HBUF + (uint32_t)(wm * 32) * S48;
        const uint32_t bbase = Bs0 + (uint32_t)bufr * HBUF + (uint32_t)(wn * 64) * S48;

        uint32_t af[2][4], bf[8][2];
        #pragma unroll
        for (int ma = 0; ma < 2; ma++)
            ldsm4(af[ma][0], af[ma][1], af[ma][2], af[ma][3],
                  abase + (uint32_t)(ma * 16) * S48 + a_lo);
        #pragma unroll
        for (int p = 0; p < 4; p++)
            ldsm4(bf[2*p][0], bf[2*p][1], bf[2*p+1][0], bf[2*p+1][1],
                  bbase + (uint32_t)(p * 16) * S48 + b_lo);
        #pragma unroll
        for (int ma = 0; ma < 2; ma++)
            #pragma unroll
            for (int nb = 0; nb < 8; nb++)
                mma16(acc[ma][nb], af[ma], bf[nb]);

        bufw = (bufw == 2) ? 0 : bufw + 1;
        __syncthreads();
    }

    #pragma unroll
    for (int ma = 0; ma < 2; ma++) {
        const int r0 = bm + wm*32 + ma*16 + g;
        #pragma unroll
        for (int nb = 0; nb < 8; nb++) {
            const int c0 = bn + wn*64 + nb*8 + 2*t;
            *(float2*)&C[(size_t)r0     * N + c0] = make_float2(acc[ma][nb][0], acc[ma][nb][1]);
            *(float2*)&C[(size_t)(r0+8) * N + c0] = make_float2(acc[ma][nb][2], acc[ma][nb][3]);
        }
    }
}

// ---------------------------------------------------------------------------
// Flash attention, fp16 mma.sync m16n8k16 (Round-11 version, unchanged).
// ---------------------------------------------------------------------------
#define ARB 144         // row stride bytes (72 fp16)

__global__ void __launch_bounds__(256) attn_h(const float* __restrict__ qkv,
                                              float* __restrict__ outp)
{
    __shared__ __align__(16) __half sh[2*64*72];
    __half* Ks = sh;                                // [64 kv][72]
    __half* Vs = sh + 64*72;                        // [64 kv][72]
    __half* Qs = sh;                                // [128 q][72] staging overlay

    const int tid = threadIdx.x;
    const int lane = tid & 31, wid = tid >> 5;
    const int g = lane >> 2, t = lane & 3;
    const int bh = blockIdx.y, b = bh >> 4, h = bh & 15;
    const int q0 = blockIdx.x * 128;
    const float* base = qkv + (size_t)b * SEQ * QKVCOL;

    const uint32_t Ks0 = smem_u32(Ks), Vs0 = smem_u32(Vs), Qs0 = smem_u32(Qs);
    const uint32_t a_lo = (uint32_t)((lane & 15) * ARB + (lane >> 4) * 16);
    const uint32_t b_lo = (uint32_t)(((lane & 7) + ((lane >> 4) & 1) * 8) * ARB + ((lane >> 3) & 1) * 16);
    const uint32_t v_lo = (uint32_t)(((lane & 7) + ((lane >> 3) & 1) * 8) * ARB + (lane >> 4) * 16);

    {
        const int r = tid >> 1, f0 = (tid & 1) * 32;
        const float* qr = base + (size_t)(q0 + r) * QKVCOL + h*DH + f0;
        uint32_t dst = Qs0 + (uint32_t)(r * ARB + f0 * 2);
        #pragma unroll
        for (int i = 0; i < 4; i++) {
            float4 q0v = ((const float4*)qr)[2*i];
            float4 q1v = ((const float4*)qr)[2*i+1];
            asm volatile("st.shared.v4.b32 [%0], {%1,%2,%3,%4};" :: "r"(dst + i*16),
                "r"(pkh(q0v.x*0.125f,q0v.y*0.125f)), "r"(pkh(q0v.z*0.125f,q0v.w*0.125f)),
                "r"(pkh(q1v.x*0.125f,q1v.y*0.125f)), "r"(pkh(q1v.z*0.125f,q1v.w*0.125f)));
        }
    }
    __syncthreads();

    uint32_t qf[4][4];
    #pragma unroll
    for (int kc = 0; kc < 4; kc++)
        ldsm4(qf[kc][0], qf[kc][1], qf[kc][2], qf[kc][3],
              Qs0 + (uint32_t)(wid * 16 * ARB + kc * 32) + a_lo);
    __syncthreads();

    float o[8][4] = {};
    float m0 = -INFINITY, m1 = -INFINITY, l0 = 0.f, l1 = 0.f;
    const int row0 = q0 + wid*16 + g;
    const int ntiles = q0/64 + 2;

    const int fr = tid & 63, fc = (tid >> 6) * 16;
    const float* Kg = base + (size_t)fr * QKVCOL +     DIM + h*DH + fc;
    const float* Vg = base + (size_t)fr * QKVCOL + 2 * DIM + h*DH + fc;
    const size_t tstep = (size_t)64 * QKVCOL;
    const uint32_t kdst = Ks0 + (uint32_t)(fr * ARB + fc * 2);
    const uint32_t vdst = Vs0 + (uint32_t)(fr * ARB + fc * 2);

    float4 rk[4], rv[4];
    #pragma unroll
    for (int i = 0; i < 4; i++) { rk[i] = ((const float4*)Kg)[i]; rv[i] = ((const float4*)Vg)[i]; }

    for (int kt = 0; kt < ntiles; kt++) {
        #pragma unroll
        for (int i = 0; i < 2; i++) {
            asm volatile("st.shared.v4.b32 [%0], {%1,%2,%3,%4};" :: "r"(kdst + i*16),
                "r"(pkh(rk[2*i].x,rk[2*i].y)), "r"(pkh(rk[2*i].z,rk[2*i].w)),
                "r"(pkh(rk[2*i+1].x,rk[2*i+1].y)), "r"(pkh(rk[2*i+1].z,rk[2*i+1].w)));
            asm volatile("st.shared.v4.b32 [%0], {%1,%2,%3,%4};" :: "r"(vdst + i*16),
                "r"(pkh(rv[2*i].x,rv[2*i].y)), "r"(pkh(rv[2*i].z,rv[2*i].w)),
                "r"(pkh(rv[2*i+1].x,rv[2*i+1].y)), "r"(pkh(rv[2*i+1].z,rv[2*i+1].w)));
        }
        __syncthreads();

        if (kt + 1 < ntiles) {
            const float* Kg2 = Kg + (size_t)(kt + 1) * tstep;
            const float* Vg2 = Vg + (size_t)(kt + 1) * tstep;
            #pragma unroll
            for (int i = 0; i < 4; i++) { rk[i] = ((const float4*)Kg2)[i]; rv[i] = ((const float4*)Vg2)[i]; }
        }

        // ---- S = Q @ K^T ----
        float s[8][4] = {};
        #pragma unroll
        for (int kc = 0; kc < 4; kc++) {
            uint32_t bk[8][2];
            #pragma unroll
            for (int p = 0; p < 4; p++)
                ldsm4(bk[2*p][0], bk[2*p][1], bk[2*p+1][0], bk[2*p+1][1],
                      Ks0 + (uint32_t)(p * 16 * ARB + kc * 32) + b_lo);
            #pragma unroll
            for (int nb = 0; nb < 8; nb++)
                mma16(s[nb], qf[kc], bk[nb]);
        }

        // ---- causal mask + online softmax ----
        const int colbase = kt*64 + 2*t;
        float t0 = -INFINITY, t1 = -INFINITY;
        #pragma unroll
        for (int na = 0; na < 8; na++) {
            const int c = colbase + na*8;
            if (c     > row0)     s[na][0] = -INFINITY;
            if (c + 1 > row0)     s[na][1] = -INFINITY;
            if (c     > row0 + 8) s[na][2] = -INFINITY;
            if (c + 1 > row0 + 8) s[na][3] = -INFINITY;
            t0 = fmaxf(t0, fmaxf(s[na][0], s[na][1]));
            t1 = fmaxf(t1, fmaxf(s[na][2], s[na][3]));
        }
        t0 = fmaxf(t0, __shfl_xor_sync(0xffffffffu, t0, 1));
        t0 = fmaxf(t0, __shfl_xor_sync(0xffffffffu, t0, 2));
        t1 = fmaxf(t1, __shfl_xor_sync(0xffffffffu, t1, 1));
        t1 = fmaxf(t1, __shfl_xor_sync(0xffffffffu, t1, 2));

        const float mn0 = fmaxf(m0, t0), mn1 = fmaxf(m1, t1);
        const float sc0 = __expf(m0 - mn0), sc1 = __expf(m1 - mn1);
        m0 = mn0; m1 = mn1; l0 *= sc0; l1 *= sc1;

        #pragma unroll
        for (int na = 0; na < 8; na++) {
            o[na][0] *= sc0; o[na][1] *= sc0; o[na][2] *= sc1; o[na][3] *= sc1;
            s[na][0] = __expf(s[na][0] - m0);
            s[na][1] = __expf(s[na][1] - m0);
            s[na][2] = __expf(s[na][2] - m1);
            s[na][3] = __expf(s[na][3] - m1);
            l0 += s[na][0] + s[na][1];
            l1 += s[na][2] + s[na][3];
        }

        // ---- O += P @ V ----
        #pragma unroll
        for (int kc = 0; kc < 4; kc++) {
            uint32_t pa[4];
            pa[0] = pkh(s[2*kc][0],   s[2*kc][1]);
            pa[1] = pkh(s[2*kc][2],   s[2*kc][3]);
            pa[2] = pkh(s[2*kc+1][0], s[2*kc+1][1]);
            pa[3] = pkh(s[2*kc+1][2], s[2*kc+1][3]);

            uint32_t bv[8][2];
            #pragma unroll
            for (int p = 0; p < 4; p++)
                ldsm4t(bv[2*p][0], bv[2*p][1], bv[2*p+1][0], bv[2*p+1][1],
                       Vs0 + (uint32_t)(kc * 16 * ARB + p * 32) + v_lo);
            #pragma unroll
            for (int nb = 0; nb < 8; nb++)
                mma16(o[nb], pa, bv[nb]);
        }
        __syncthreads();
    }

    l0 += __shfl_xor_sync(0xffffffffu, l0, 1);
    l0 += __shfl_xor_sync(0xffffffffu, l0, 2);
    l1 += __shfl_xor_sync(0xffffffffu, l1, 1);
    l1 += __shfl_xor_sync(0xffffffffu, l1, 2);
    const float i0 = 1.f / l0, i1 = 1.f / l1;

    float* orow0 = outp + (size_t)(b*SEQ + row0) * DIM + h*DH;
    float* orow1 = orow0 + 8*DIM;
    #pragma unroll
    for (int na = 0; na < 8; na++) {
        *(float2*)&orow0[na*8 + 2*t] = make_float2(o[na][0]*i0, o[na][1]*i0);
        *(float2*)&orow1[na*8 + 2*t] = make_float2(o[na][2]*i1, o[na][3]*i1);
    }
}

// ---------------------------------------------------------------------------
extern "C" void kernel_launch(void* const* d_in, const int* in_sizes, int n_in,
                              void* d_out, int out_size)
{
    const float* x     = (const float*)d_in[0];
    const float* W_qkv = (const float*)d_in[1];
    const float* W_out = (const float*)d_in[2];
    float*       out   = (float*)d_out;

    float *qkv, *attn;
    cudaGetSymbolAddress((void**)&qkv,  g_qkv);
    cudaGetSymbolAddress((void**)&attn, g_attn);

    // 1) qkv = x @ W_qkv^T
    gemm_h<<<dim3(QKVCOL/128, MROWS/128), 256>>>(x, W_qkv, qkv, MROWS, QKVCOL, DIM);
    // 2) causal attention
    attn_h<<<dim3(SEQ/128, BATCH*HEADS), 256>>>(qkv, attn);
    // 3) out = attn @ W_out^T
    gemm_h<<<dim3(DIM/128, MROWS/128), 256>>>(attn, W_out, out, MROWS, DIM, DIM);
}

// round 15
// speedup vs baseline: 2.8478x; 1.2498x over previous
#include <cuda_runtime.h>
#include <cuda_fp16.h>
#include <math.h>
#include <stdint.h>

#define SEQ    2048
#define BATCH  2
#define DIM    1024
#define HEADS  16
#define DH     64
#define MROWS  (BATCH*SEQ)          // 4096
#define QKVCOL (3*DIM)              // 3072

__device__ __half g_qkvh[MROWS * QKVCOL];   // fp16 qkv (Q pre-scaled by 1/8)
__device__ __half g_attnh[MROWS * DIM];     // fp16 attention output
__device__ __half g_xh  [MROWS * DIM];
__device__ __half g_wqh [QKVCOL * DIM];
__device__ __half g_woh [DIM * DIM];

// ---------------------------------------------------------------------------
__device__ __forceinline__ uint32_t smem_u32(const void* p){
    return (uint32_t)__cvta_generic_to_shared(p);
}
__device__ __forceinline__ uint32_t pkh(float lo, float hi){
    __half2 h = __floats2half2_rn(lo, hi);
    return *reinterpret_cast<uint32_t*>(&h);
}
__device__ __forceinline__ void mma16(float* c, const uint32_t* a, const uint32_t* b){
    asm volatile("mma.sync.aligned.m16n8k16.row.col.f32.f16.f16.f32 "
        "{%0,%1,%2,%3}, {%4,%5,%6,%7}, {%8,%9}, {%0,%1,%2,%3};"
        : "+f"(c[0]),"+f"(c[1]),"+f"(c[2]),"+f"(c[3])
        : "r"(a[0]),"r"(a[1]),"r"(a[2]),"r"(a[3]),"r"(b[0]),"r"(b[1]));
}
__device__ __forceinline__ void ldsm4(uint32_t& r0, uint32_t& r1, uint32_t& r2, uint32_t& r3,
                                      uint32_t addr){
    asm volatile("ldmatrix.sync.aligned.m8n8.x4.shared.b16 {%0,%1,%2,%3}, [%4];"
        : "=r"(r0),"=r"(r1),"=r"(r2),"=r"(r3) : "r"(addr));
}
__device__ __forceinline__ void ldsm4t(uint32_t& r0, uint32_t& r1, uint32_t& r2, uint32_t& r3,
                                       uint32_t addr){
    asm volatile("ldmatrix.sync.aligned.m8n8.x4.trans.shared.b16 {%0,%1,%2,%3}, [%4];"
        : "=r"(r0),"=r"(r1),"=r"(r2),"=r"(r3) : "r"(addr));
}
#define STS16(addr, v) \
    asm volatile("st.shared.v4.b32 [%0], {%1,%2,%3,%4};" :: "r"(addr), \
                 "r"((v).x), "r"((v).y), "r"((v).z), "r"((v).w))

// ---------------------------------------------------------------------------
// fp32 -> fp16 convert, 8 elems/thread
// ---------------------------------------------------------------------------
__global__ void cvt_h(const float* __restrict__ in, __half* __restrict__ out, int n8)
{
    int i = blockIdx.x * blockDim.x + threadIdx.x;
    if (i < n8) {
        float4 a = ((const float4*)in)[2*i];
        float4 b = ((const float4*)in)[2*i+1];
        uint4 r;
        r.x = pkh(a.x, a.y); r.y = pkh(a.z, a.w);
        r.z = pkh(b.x, b.y); r.w = pkh(b.z, b.w);
        ((uint4*)out)[i] = r;
    }
}

// ---------------------------------------------------------------------------
// fp16 GEMM, 3-stage smem pipeline: C[M,N] = A[M,K] @ B[N,K]^T.
// A,B fp16. Output: fp16 (Ch) or fp32 (Cf). Columns < scale_cols scaled 0.125.
// CTA 128x128, 256 threads (8 warps 4x2), warp tile 32x64, BK=16.
// ---------------------------------------------------------------------------
#define S48  48u
#define HBUF (128*S48)

__global__ void __launch_bounds__(256,2) gemm_h16(const __half* __restrict__ A,
                                                  const __half* __restrict__ B,
                                                  __half* __restrict__ Ch,
                                                  float* __restrict__ Cf,
                                                  int M, int N, int K, int scale_cols)
{
    __shared__ __align__(16) unsigned char As[3][HBUF];
    __shared__ __align__(16) unsigned char Bs[3][HBUF];

    const int tid  = threadIdx.x;
    const int lane = tid & 31, wid = tid >> 5;
    const int g = lane >> 2, t = lane & 3;
    const int wm = wid & 3, wn = wid >> 2;
    const int bm = blockIdx.y * 128, bn = blockIdx.x * 128;

    const uint32_t As0 = smem_u32(As), Bs0 = smem_u32(Bs);
    const uint32_t a_lo = (uint32_t)((lane & 15) * S48 + (lane >> 4) * 16);
    const uint32_t b_lo = (uint32_t)(((lane & 7) + ((lane >> 4) & 1) * 8) * S48 + ((lane >> 3) & 1) * 16);

    // fill: thread owns row tid>>1, 8 fp16 (16B) at k-offset (tid&1)*8
    const int frow = tid >> 1;
    const __half* Ag = A + (size_t)(bm + frow) * K + (tid & 1) * 8;
    const __half* Bg = B + (size_t)(bn + frow) * K + (tid & 1) * 8;
    const uint32_t sA = As0 + (uint32_t)(frow * S48 + (tid & 1) * 16);
    const uint32_t sB = Bs0 + (uint32_t)(frow * S48 + (tid & 1) * 16);

    float acc[2][8][4] = {};
    const int NC = K / 16;

    // prologue: chunk 0 -> buf 0, chunk 1 -> regs
    uint4 ra = *(const uint4*)Ag, rb = *(const uint4*)Bg;
    STS16(sA, ra);
    STS16(sB, rb);
    ra = *(const uint4*)(Ag + 16);
    rb = *(const uint4*)(Bg + 16);
    __syncthreads();

    int bufw = 1;
    for (int c = 0; c < NC; c++) {
        if (c + 1 < NC) {
            STS16(sA + (uint32_t)bufw * HBUF, ra);
            STS16(sB + (uint32_t)bufw * HBUF, rb);
        }
        if (c + 2 < NC) {
            ra = *(const uint4*)(Ag + (c + 2) * 16);
            rb = *(const uint4*)(Bg + (c + 2) * 16);
        }

        const int bufr = (bufw + 2) % 3;
        const uint32_t abase = As0 + (uint32_t)bufr * HBUF + (uint32_t)(wm * 32) * S48;
        const uint32_t bbase = Bs0 + (uint32_t)bufr * HBUF + (uint32_t)(wn * 64) * S48;

        uint32_t af[2][4], bf[8][2];
        #pragma unroll
        for (int ma = 0; ma < 2; ma++)
            ldsm4(af[ma][0], af[ma][1], af[ma][2], af[ma][3],
                  abase + (uint32_t)(ma * 16) * S48 + a_lo);
        #pragma unroll
        for (int p = 0; p < 4; p++)
            ldsm4(bf[2*p][0], bf[2*p][1], bf[2*p+1][0], bf[2*p+1][1],
                  bbase + (uint32_t)(p * 16) * S48 + b_lo);
        #pragma unroll
        for (int ma = 0; ma < 2; ma++)
            #pragma unroll
            for (int nb = 0; nb < 8; nb++)
                mma16(acc[ma][nb], af[ma], bf[nb]);

        bufw = (bufw == 2) ? 0 : bufw + 1;
        __syncthreads();
    }

    if (Ch) {
        #pragma unroll
        for (int ma = 0; ma < 2; ma++) {
            const int r0 = bm + wm*32 + ma*16 + g;
            #pragma unroll
            for (int nb = 0; nb < 8; nb++) {
                const int c0 = bn + wn*64 + nb*8 + 2*t;
                const float sc = (c0 < scale_cols) ? 0.125f : 1.0f;
                *(uint32_t*)&Ch[(size_t)r0     * N + c0] = pkh(acc[ma][nb][0]*sc, acc[ma][nb][1]*sc);
                *(uint32_t*)&Ch[(size_t)(r0+8) * N + c0] = pkh(acc[ma][nb][2]*sc, acc[ma][nb][3]*sc);
            }
        }
    } else {
        #pragma unroll
        for (int ma = 0; ma < 2; ma++) {
            const int r0 = bm + wm*32 + ma*16 + g;
            #pragma unroll
            for (int nb = 0; nb < 8; nb++) {
                const int c0 = bn + wn*64 + nb*8 + 2*t;
                *(float2*)&Cf[(size_t)r0     * N + c0] = make_float2(acc[ma][nb][0], acc[ma][nb][1]);
                *(float2*)&Cf[(size_t)(r0+8) * N + c0] = make_float2(acc[ma][nb][2], acc[ma][nb][3]);
            }
        }
    }
}

// ---------------------------------------------------------------------------
// Flash attention, fp16 in/out. Q pre-scaled in gemm1 epilogue.
// Fill paths are plain 16B copies (no cvt). Output fp16.
// ---------------------------------------------------------------------------
#define ARB 144         // row stride bytes (72 fp16)

__global__ void __launch_bounds__(256) attn_h16(const __half* __restrict__ qkv,
                                                __half* __restrict__ outp)
{
    __shared__ __align__(16) __half sh[2*64*72];    // 18432 B
    __half* Ks = sh;                                // [64 kv][72]
    __half* Vs = sh + 64*72;                        // [64 kv][72]
    __half* Qs = sh;                                // [128 q][72] staging overlay

    const int tid = threadIdx.x;
    const int lane = tid & 31, wid = tid >> 5;
    const int g = lane >> 2, t = lane & 3;
    const int bh = blockIdx.y, b = bh >> 4, h = bh & 15;
    const int q0 = blockIdx.x * 128;
    const __half* base = qkv + (size_t)b * SEQ * QKVCOL;

    const uint32_t Ks0 = smem_u32(Ks), Vs0 = smem_u32(Vs), Qs0 = smem_u32(Qs);
    const uint32_t a_lo = (uint32_t)((lane & 15) * ARB + (lane >> 4) * 16);
    const uint32_t b_lo = (uint32_t)(((lane & 7) + ((lane >> 4) & 1) * 8) * ARB + ((lane >> 3) & 1) * 16);
    const uint32_t v_lo = (uint32_t)(((lane & 7) + ((lane >> 3) & 1) * 8) * ARB + (lane >> 4) * 16);

    // stage Q (already scaled): plain copy, 64B per thread
    {
        const int r = tid >> 1;
        const __half* qr = base + (size_t)(q0 + r) * QKVCOL + h*DH + (tid & 1) * 32;
        const uint32_t dst = Qs0 + (uint32_t)(r * ARB + (tid & 1) * 64);
        #pragma unroll
        for (int i = 0; i < 4; i++) {
            uint4 v = ((const uint4*)qr)[i];
            STS16(dst + i*16, v);
        }
    }
    __syncthreads();

    uint32_t qf[4][4];
    #pragma unroll
    for (int kc = 0; kc < 4; kc++)
        ldsm4(qf[kc][0], qf[kc][1], qf[kc][2], qf[kc][3],
              Qs0 + (uint32_t)(wid * 16 * ARB + kc * 32) + a_lo);
    __syncthreads();

    float o[8][4] = {};
    float m0 = -INFINITY, m1 = -INFINITY, l0 = 0.f, l1 = 0.f;
    const int row0 = q0 + wid*16 + g;
    const int ntiles = q0/64 + 2;

    // fill mapping: row tid&63, 16 fp16 (32B) at col offset (tid>>6)*16
    const int fr = tid & 63, fc = (tid >> 6) * 16;
    const __half* Kg = base + (size_t)fr * QKVCOL +     DIM + h*DH + fc;
    const __half* Vg = base + (size_t)fr * QKVCOL + 2 * DIM + h*DH + fc;
    const size_t tstep = (size_t)64 * QKVCOL;
    const uint32_t kdst = Ks0 + (uint32_t)(fr * ARB + fc * 2);
    const uint32_t vdst = Vs0 + (uint32_t)(fr * ARB + fc * 2);

    uint4 rk[2], rv[2];
    #pragma unroll
    for (int i = 0; i < 2; i++) { rk[i] = ((const uint4*)Kg)[i]; rv[i] = ((const uint4*)Vg)[i]; }

    for (int kt = 0; kt < ntiles; kt++) {
        #pragma unroll
        for (int i = 0; i < 2; i++) {
            STS16(kdst + i*16, rk[i]);
            STS16(vdst + i*16, rv[i]);
        }
        __syncthreads();

        if (kt + 1 < ntiles) {
            const __half* Kg2 = Kg + (size_t)(kt + 1) * tstep;
            const __half* Vg2 = Vg + (size_t)(kt + 1) * tstep;
            #pragma unroll
            for (int i = 0; i < 2; i++) { rk[i] = ((const uint4*)Kg2)[i]; rv[i] = ((const uint4*)Vg2)[i]; }
        }

        // ---- S = Q @ K^T ----
        float s[8][4] = {};
        #pragma unroll
        for (int kc = 0; kc < 4; kc++) {
            uint32_t bk[8][2];
            #pragma unroll
            for (int p = 0; p < 4; p++)
                ldsm4(bk[2*p][0], bk[2*p][1], bk[2*p+1][0], bk[2*p+1][1],
                      Ks0 + (uint32_t)(p * 16 * ARB + kc * 32) + b_lo);
            #pragma unroll
            for (int nb = 0; nb < 8; nb++)
                mma16(s[nb], qf[kc], bk[nb]);
        }

        // ---- causal mask + online softmax ----
        const int colbase = kt*64 + 2*t;
        float t0 = -INFINITY, t1 = -INFINITY;
        #pragma unroll
        for (int na = 0; na < 8; na++) {
            const int c = colbase + na*8;
            if (c     > row0)     s[na][0] = -INFINITY;
            if (c + 1 > row0)     s[na][1] = -INFINITY;
            if (c     > row0 + 8) s[na][2] = -INFINITY;
            if (c + 1 > row0 + 8) s[na][3] = -INFINITY;
            t0 = fmaxf(t0, fmaxf(s[na][0], s[na][1]));
            t1 = fmaxf(t1, fmaxf(s[na][2], s[na][3]));
        }
        t0 = fmaxf(t0, __shfl_xor_sync(0xffffffffu, t0, 1));
        t0 = fmaxf(t0, __shfl_xor_sync(0xffffffffu, t0, 2));
        t1 = fmaxf(t1, __shfl_xor_sync(0xffffffffu, t1, 1));
        t1 = fmaxf(t1, __shfl_xor_sync(0xffffffffu, t1, 2));

        const float mn0 = fmaxf(m0, t0), mn1 = fmaxf(m1, t1);
        const float sc0 = __expf(m0 - mn0), sc1 = __expf(m1 - mn1);
        m0 = mn0; m1 = mn1; l0 *= sc0; l1 *= sc1;

        #pragma unroll
        for (int na = 0; na < 8; na++) {
            o[na][0] *= sc0; o[na][1] *= sc0; o[na][2] *= sc1; o[na][3] *= sc1;
            s[na][0] = __expf(s[na][0] - m0);
            s[na][1] = __expf(s[na][1] - m0);
            s[na][2] = __expf(s[na][2] - m1);
            s[na][3] = __expf(s[na][3] - m1);
            l0 += s[na][0] + s[na][1];
            l1 += s[na][2] + s[na][3];
        }

        // ---- O += P @ V ----
        #pragma unroll
        for (int kc = 0; kc < 4; kc++) {
            uint32_t pa[4];
            pa[0] = pkh(s[2*kc][0],   s[2*kc][1]);
            pa[1] = pkh(s[2*kc][2],   s[2*kc][3]);
            pa[2] = pkh(s[2*kc+1][0], s[2*kc+1][1]);
            pa[3] = pkh(s[2*kc+1][2], s[2*kc+1][3]);

            uint32_t bv[8][2];
            #pragma unroll
            for (int p = 0; p < 4; p++)
                ldsm4t(bv[2*p][0], bv[2*p][1], bv[2*p+1][0], bv[2*p+1][1],
                       Vs0 + (uint32_t)(kc * 16 * ARB + p * 32) + v_lo);
            #pragma unroll
            for (int nb = 0; nb < 8; nb++)
                mma16(o[nb], pa, bv[nb]);
        }
        __syncthreads();
    }

    l0 += __shfl_xor_sync(0xffffffffu, l0, 1);
    l0 += __shfl_xor_sync(0xffffffffu, l0, 2);
    l1 += __shfl_xor_sync(0xffffffffu, l1, 1);
    l1 += __shfl_xor_sync(0xffffffffu, l1, 2);
    const float i0 = 1.f / l0, i1 = 1.f / l1;

    __half* orow0 = outp + (size_t)(b*SEQ + row0) * DIM + h*DH;
    __half* orow1 = orow0 + 8*DIM;
    #pragma unroll
    for (int na = 0; na < 8; na++) {
        *(uint32_t*)&orow0[na*8 + 2*t] = pkh(o[na][0]*i0, o[na][1]*i0);
        *(uint32_t*)&orow1[na*8 + 2*t] = pkh(o[na][2]*i1, o[na][3]*i1);
    }
}

// ---------------------------------------------------------------------------
extern "C" void kernel_launch(void* const* d_in, const int* in_sizes, int n_in,
                              void* d_out, int out_size)
{
    const float* x     = (const float*)d_in[0];
    const float* W_qkv = (const float*)d_in[1];
    const float* W_out = (const float*)d_in[2];
    float*       out   = (float*)d_out;

    __half *qkvh, *attnh, *xh, *wqh, *woh;
    cudaGetSymbolAddress((void**)&qkvh,  g_qkvh);
    cudaGetSymbolAddress((void**)&attnh, g_attnh);
    cudaGetSymbolAddress((void**)&xh,    g_xh);
    cudaGetSymbolAddress((void**)&wqh,   g_wqh);
    cudaGetSymbolAddress((void**)&woh,   g_woh);

    // 0) convert inputs to fp16
    cvt_h<<<(MROWS*DIM/8 + 255)/256, 256>>>(x,     xh,  MROWS*DIM/8);
    cvt_h<<<(QKVCOL*DIM/8 + 255)/256, 256>>>(W_qkv, wqh, QKVCOL*DIM/8);
    cvt_h<<<(DIM*DIM/8 + 255)/256, 256>>>(W_out,  woh, DIM*DIM/8);

    // 1) qkv = x @ W_qkv^T (fp16 out; Q columns pre-scaled by 1/8)
    gemm_h16<<<dim3(QKVCOL/128, MROWS/128), 256>>>(xh, wqh, qkvh, nullptr,
                                                   MROWS, QKVCOL, DIM, DIM);
    // 2) causal attention (fp16 in/out)
    attn_h16<<<dim3(SEQ/128, BATCH*HEADS), 256>>>(qkvh, attnh);
    // 3) out = attn @ W_out^T (fp32 out)
    gemm_h16<<<dim3(DIM/128, MROWS/128), 256>>>(attnh, woh, nullptr, out,
                                                MROWS, DIM, DIM, 0);
}

// round 16
// speedup vs baseline: 2.8999x; 1.0183x over previous
#include <cuda_runtime.h>
#include <cuda_fp16.h>
#include <math.h>
#include <stdint.h>

#define SEQ    2048
#define BATCH  2
#define DIM    1024
#define HEADS  16
#define DH     64
#define MROWS  (BATCH*SEQ)          // 4096
#define QKVCOL (3*DIM)              // 3072

__device__ __half g_qkvh[MROWS * QKVCOL];   // fp16 qkv (Q pre-scaled by 1/8)
__device__ __half g_attnh[MROWS * DIM];     // fp16 attention output
__device__ __half g_xh  [MROWS * DIM];
__device__ __half g_wqh [QKVCOL * DIM];
__device__ __half g_woh [DIM * DIM];

// ---------------------------------------------------------------------------
__device__ __forceinline__ uint32_t smem_u32(const void* p){
    return (uint32_t)__cvta_generic_to_shared(p);
}
__device__ __forceinline__ uint32_t pkh(float lo, float hi){
    __half2 h = __floats2half2_rn(lo, hi);
    return *reinterpret_cast<uint32_t*>(&h);
}
__device__ __forceinline__ void mma16(float* c, const uint32_t* a, const uint32_t* b){
    asm volatile("mma.sync.aligned.m16n8k16.row.col.f32.f16.f16.f32 "
        "{%0,%1,%2,%3}, {%4,%5,%6,%7}, {%8,%9}, {%0,%1,%2,%3};"
        : "+f"(c[0]),"+f"(c[1]),"+f"(c[2]),"+f"(c[3])
        : "r"(a[0]),"r"(a[1]),"r"(a[2]),"r"(a[3]),"r"(b[0]),"r"(b[1]));
}
__device__ __forceinline__ void ldsm4(uint32_t& r0, uint32_t& r1, uint32_t& r2, uint32_t& r3,
                                      uint32_t addr){
    asm volatile("ldmatrix.sync.aligned.m8n8.x4.shared.b16 {%0,%1,%2,%3}, [%4];"
        : "=r"(r0),"=r"(r1),"=r"(r2),"=r"(r3) : "r"(addr));
}
__device__ __forceinline__ void ldsm4t(uint32_t& r0, uint32_t& r1, uint32_t& r2, uint32_t& r3,
                                       uint32_t addr){
    asm volatile("ldmatrix.sync.aligned.m8n8.x4.trans.shared.b16 {%0,%1,%2,%3}, [%4];"
        : "=r"(r0),"=r"(r1),"=r"(r2),"=r"(r3) : "r"(addr));
}
#define STS16(addr, v) \
    asm volatile("st.shared.v4.b32 [%0], {%1,%2,%3,%4};" :: "r"(addr), \
                 "r"((v).x), "r"((v).y), "r"((v).z), "r"((v).w))

// ---------------------------------------------------------------------------
// fused fp32 -> fp16 convert for all three inputs
// ---------------------------------------------------------------------------
__global__ void cvt3(const float* __restrict__ a, __half* __restrict__ oa, int na8,
                     const float* __restrict__ b, __half* __restrict__ ob, int nb8,
                     const float* __restrict__ c, __half* __restrict__ oc, int nc8)
{
    int i = blockIdx.x * blockDim.x + threadIdx.x;
    const float* src; __half* dst; int j;
    if (i < na8)            { src = a; dst = oa; j = i; }
    else if (i < na8 + nb8) { src = b; dst = ob; j = i - na8; }
    else if (i < na8 + nb8 + nc8) { src = c; dst = oc; j = i - na8 - nb8; }
    else return;
    float4 v0 = ((const float4*)src)[2*j];
    float4 v1 = ((const float4*)src)[2*j+1];
    uint4 r;
    r.x = pkh(v0.x, v0.y); r.y = pkh(v0.z, v0.w);
    r.z = pkh(v1.x, v1.y); r.w = pkh(v1.z, v1.w);
    ((uint4*)dst)[j] = r;
}

// ---------------------------------------------------------------------------
// fp16 GEMM, BK=32, 3-stage smem pipeline: C[M,N] = A[M,K] @ B[N,K]^T.
// CTA 128x128, 256 threads (8 warps 4x2), warp tile 32x64.
// Row stride 112B (7*16 -> conflict-free ldmatrix). Dynamic smem 84KB.
// ---------------------------------------------------------------------------
#define S112  112u
#define MBUF  (128*S112)          // 14336 B per matrix per stage
#define STGB  (2*MBUF)            // 28672 B per stage
#define G_SMEM (3*STGB)           // 86016 B

__global__ void __launch_bounds__(256,2) gemm_h16(const __half* __restrict__ A,
                                                  const __half* __restrict__ B,
                                                  __half* __restrict__ Ch,
                                                  float* __restrict__ Cf,
                                                  int M, int N, int K, int scale_cols)
{
    extern __shared__ __align__(16) unsigned char smem[];
    const uint32_t sb = smem_u32(smem);

    const int tid  = threadIdx.x;
    const int lane = tid & 31, wid = tid >> 5;
    const int g = lane >> 2, t = lane & 3;
    const int wm = wid & 3, wn = wid >> 2;
    const int bm = blockIdx.y * 128, bn = blockIdx.x * 128;

    const uint32_t a_lo = (uint32_t)((lane & 15) * S112 + (lane >> 4) * 16);
    const uint32_t b_lo = (uint32_t)(((lane & 7) + ((lane >> 4) & 1) * 8) * S112 + ((lane >> 3) & 1) * 16);

    // fill: thread owns row tid>>1, 16 fp16 (32B) at k-offset (tid&1)*16
    const int frow = tid >> 1;
    const __half* Ag = A + (size_t)(bm + frow) * K + (tid & 1) * 16;
    const __half* Bg = B + (size_t)(bn + frow) * K + (tid & 1) * 16;
    const uint32_t sA = sb + (uint32_t)(frow * S112 + (tid & 1) * 32);
    const uint32_t sB = sA + MBUF;

    float acc[2][8][4] = {};
    const int NC = K / 32;         // 32 iterations

    // prologue: chunk 0 -> buf 0, chunk 1 -> regs
    uint4 ra0 = ((const uint4*)Ag)[0], ra1 = ((const uint4*)Ag)[1];
    uint4 rb0 = ((const uint4*)Bg)[0], rb1 = ((const uint4*)Bg)[1];
    STS16(sA, ra0); STS16(sA + 16, ra1);
    STS16(sB, rb0); STS16(sB + 16, rb1);
    ra0 = ((const uint4*)(Ag + 32))[0]; ra1 = ((const uint4*)(Ag + 32))[1];
    rb0 = ((const uint4*)(Bg + 32))[0]; rb1 = ((const uint4*)(Bg + 32))[1];
    __syncthreads();

    int bufw = 1;
    for (int c = 0; c < NC; c++) {
        if (c + 1 < NC) {
            const uint32_t dA = sA + (uint32_t)bufw * STGB;
            const uint32_t dB = sB + (uint32_t)bufw * STGB;
            STS16(dA, ra0); STS16(dA + 16, ra1);
            STS16(dB, rb0); STS16(dB + 16, rb1);
        }
        if (c + 2 < NC) {
            const __half* Ag2 = Ag + (c + 2) * 32;
            const __half* Bg2 = Bg + (c + 2) * 32;
            ra0 = ((const uint4*)Ag2)[0]; ra1 = ((const uint4*)Ag2)[1];
            rb0 = ((const uint4*)Bg2)[0]; rb1 = ((const uint4*)Bg2)[1];
        }

        const int bufr = (bufw + 2) % 3;
        const uint32_t abase = sb + (uint32_t)bufr * STGB + (uint32_t)(wm * 32) * S112;
        const uint32_t bbase = abase + MBUF + (uint32_t)(wn * 64 - wm * 32) * S112;

        #pragma unroll
        for (int ks = 0; ks < 2; ks++) {
            uint32_t af[2][4], bf[8][2];
            #pragma unroll
            for (int ma = 0; ma < 2; ma++)
                ldsm4(af[ma][0], af[ma][1], af[ma][2], af[ma][3],
                      abase + (uint32_t)(ma * 16) * S112 + (uint32_t)(ks * 32) + a_lo);
            #pragma unroll
            for (int p = 0; p < 4; p++)
                ldsm4(bf[2*p][0], bf[2*p][1], bf[2*p+1][0], bf[2*p+1][1],
                      bbase + (uint32_t)(p * 16) * S112 + (uint32_t)(ks * 32) + b_lo);
            #pragma unroll
            for (int ma = 0; ma < 2; ma++)
                #pragma unroll
                for (int nb = 0; nb < 8; nb++)
                    mma16(acc[ma][nb], af[ma], bf[nb]);
        }

        bufw = (bufw == 2) ? 0 : bufw + 1;
        __syncthreads();
    }

    if (Ch) {
        #pragma unroll
        for (int ma = 0; ma < 2; ma++) {
            const int r0 = bm + wm*32 + ma*16 + g;
            #pragma unroll
            for (int nb = 0; nb < 8; nb++) {
                const int c0 = bn + wn*64 + nb*8 + 2*t;
                const float sc = (c0 < scale_cols) ? 0.125f : 1.0f;
                *(uint32_t*)&Ch[(size_t)r0     * N + c0] = pkh(acc[ma][nb][0]*sc, acc[ma][nb][1]*sc);
                *(uint32_t*)&Ch[(size_t)(r0+8) * N + c0] = pkh(acc[ma][nb][2]*sc, acc[ma][nb][3]*sc);
            }
        }
    } else {
        #pragma unroll
        for (int ma = 0; ma < 2; ma++) {
            const int r0 = bm + wm*32 + ma*16 + g;
            #pragma unroll
            for (int nb = 0; nb < 8; nb++) {
                const int c0 = bn + wn*64 + nb*8 + 2*t;
                *(float2*)&Cf[(size_t)r0     * N + c0] = make_float2(acc[ma][nb][0], acc[ma][nb][1]);
                *(float2*)&Cf[(size_t)(r0+8) * N + c0] = make_float2(acc[ma][nb][2], acc[ma][nb][3]);
            }
        }
    }
}

// ---------------------------------------------------------------------------
// Flash attention, fp16 in/out, longest-tiles-first scheduling.
// ---------------------------------------------------------------------------
#define ARB 144         // row stride bytes (72 fp16)

__global__ void __launch_bounds__(256) attn_h16(const __half* __restrict__ qkv,
                                                __half* __restrict__ outp)
{
    __shared__ __align__(16) __half sh[2*64*72];    // 18432 B
    __half* Ks = sh;                                // [64 kv][72]
    __half* Vs = sh + 64*72;                        // [64 kv][72]
    __half* Qs = sh;                                // [128 q][72] staging overlay

    const int tid = threadIdx.x;
    const int lane = tid & 31, wid = tid >> 5;
    const int g = lane >> 2, t = lane & 3;
    const int bh = blockIdx.y, b = bh >> 4, h = bh & 15;
    const int q0 = (gridDim.x - 1 - blockIdx.x) * 128;   // longest first
    const __half* base = qkv + (size_t)b * SEQ * QKVCOL;

    const uint32_t Ks0 = smem_u32(Ks), Vs0 = smem_u32(Vs), Qs0 = smem_u32(Qs);
    const uint32_t a_lo = (uint32_t)((lane & 15) * ARB + (lane >> 4) * 16);
    const uint32_t b_lo = (uint32_t)(((lane & 7) + ((lane >> 4) & 1) * 8) * ARB + ((lane >> 3) & 1) * 16);
    const uint32_t v_lo = (uint32_t)(((lane & 7) + ((lane >> 3) & 1) * 8) * ARB + (lane >> 4) * 16);

    // stage Q (already scaled): plain copy
    {
        const int r = tid >> 1;
        const __half* qr = base + (size_t)(q0 + r) * QKVCOL + h*DH + (tid & 1) * 32;
        const uint32_t dst = Qs0 + (uint32_t)(r * ARB + (tid & 1) * 64);
        #pragma unroll
        for (int i = 0; i < 4; i++) {
            uint4 v = ((const uint4*)qr)[i];
            STS16(dst + i*16, v);
        }
    }
    __syncthreads();

    uint32_t qf[4][4];
    #pragma unroll
    for (int kc = 0; kc < 4; kc++)
        ldsm4(qf[kc][0], qf[kc][1], qf[kc][2], qf[kc][3],
              Qs0 + (uint32_t)(wid * 16 * ARB + kc * 32) + a_lo);
    __syncthreads();

    float o[8][4] = {};
    float m0 = -INFINITY, m1 = -INFINITY, l0 = 0.f, l1 = 0.f;
    const int row0 = q0 + wid*16 + g;
    const int ntiles = q0/64 + 2;

    const int fr = tid & 63, fc = (tid >> 6) * 16;
    const __half* Kg = base + (size_t)fr * QKVCOL +     DIM + h*DH + fc;
    const __half* Vg = base + (size_t)fr * QKVCOL + 2 * DIM + h*DH + fc;
    const size_t tstep = (size_t)64 * QKVCOL;
    const uint32_t kdst = Ks0 + (uint32_t)(fr * ARB + fc * 2);
    const uint32_t vdst = Vs0 + (uint32_t)(fr * ARB + fc * 2);

    uint4 rk[2], rv[2];
    #pragma unroll
    for (int i = 0; i < 2; i++) { rk[i] = ((const uint4*)Kg)[i]; rv[i] = ((const uint4*)Vg)[i]; }

    for (int kt = 0; kt < ntiles; kt++) {
        #pragma unroll
        for (int i = 0; i < 2; i++) {
            STS16(kdst + i*16, rk[i]);
            STS16(vdst + i*16, rv[i]);
        }
        __syncthreads();

        if (kt + 1 < ntiles) {
            const __half* Kg2 = Kg + (size_t)(kt + 1) * tstep;
            const __half* Vg2 = Vg + (size_t)(kt + 1) * tstep;
            #pragma unroll
            for (int i = 0; i < 2; i++) { rk[i] = ((const uint4*)Kg2)[i]; rv[i] = ((const uint4*)Vg2)[i]; }
        }

        // ---- S = Q @ K^T ----
        float s[8][4] = {};
        #pragma unroll
        for (int kc = 0; kc < 4; kc++) {
            uint32_t bk[8][2];
            #pragma unroll
            for (int p = 0; p < 4; p++)
                ldsm4(bk[2*p][0], bk[2*p][1], bk[2*p+1][0], bk[2*p+1][1],
                      Ks0 + (uint32_t)(p * 16 * ARB + kc * 32) + b_lo);
            #pragma unroll
            for (int nb = 0; nb < 8; nb++)
                mma16(s[nb], qf[kc], bk[nb]);
        }

        // ---- causal mask + online softmax ----
        const int colbase = kt*64 + 2*t;
        float t0 = -INFINITY, t1 = -INFINITY;
        #pragma unroll
        for (int na = 0; na < 8; na++) {
            const int c = colbase + na*8;
            if (c     > row0)     s[na][0] = -INFINITY;
            if (c + 1 > row0)     s[na][1] = -INFINITY;
            if (c     > row0 + 8) s[na][2] = -INFINITY;
            if (c + 1 > row0 + 8) s[na][3] = -INFINITY;
            t0 = fmaxf(t0, fmaxf(s[na][0], s[na][1]));
            t1 = fmaxf(t1, fmaxf(s[na][2], s[na][3]));
        }
        t0 = fmaxf(t0, __shfl_xor_sync(0xffffffffu, t0, 1));
        t0 = fmaxf(t0, __shfl_xor_sync(0xffffffffu, t0, 2));
        t1 = fmaxf(t1, __shfl_xor_sync(0xffffffffu, t1, 1));
        t1 = fmaxf(t1, __shfl_xor_sync(0xffffffffu, t1, 2));

        const float mn0 = fmaxf(m0, t0), mn1 = fmaxf(m1, t1);
        const float sc0 = __expf(m0 - mn0), sc1 = __expf(m1 - mn1);
        m0 = mn0; m1 = mn1; l0 *= sc0; l1 *= sc1;

        #pragma unroll
        for (int na = 0; na < 8; na++) {
            o[na][0] *= sc0; o[na][1] *= sc0; o[na][2] *= sc1; o[na][3] *= sc1;
            s[na][0] = __expf(s[na][0] - m0);
            s[na][1] = __expf(s[na][1] - m0);
            s[na][2] = __expf(s[na][2] - m1);
            s[na][3] = __expf(s[na][3] - m1);
            l0 += s[na][0] + s[na][1];
            l1 += s[na][2] + s[na][3];
        }

        // ---- O += P @ V ----
        #pragma unroll
        for (int kc = 0; kc < 4; kc++) {
            uint32_t pa[4];
            pa[0] = pkh(s[2*kc][0],   s[2*kc][1]);
            pa[1] = pkh(s[2*kc][2],   s[2*kc][3]);
            pa[2] = pkh(s[2*kc+1][0], s[2*kc+1][1]);
            pa[3] = pkh(s[2*kc+1][2], s[2*kc+1][3]);

            uint32_t bv[8][2];
            #pragma unroll
            for (int p = 0; p < 4; p++)
                ldsm4t(bv[2*p][0], bv[2*p][1], bv[2*p+1][0], bv[2*p+1][1],
                       Vs0 + (uint32_t)(kc * 16 * ARB + p * 32) + v_lo);
            #pragma unroll
            for (int nb = 0; nb < 8; nb++)
                mma16(o[nb], pa, bv[nb]);
        }
        __syncthreads();
    }

    l0 += __shfl_xor_sync(0xffffffffu, l0, 1);
    l0 += __shfl_xor_sync(0xffffffffu, l0, 2);
    l1 += __shfl_xor_sync(0xffffffffu, l1, 1);
    l1 += __shfl_xor_sync(0xffffffffu, l1, 2);
    const float i0 = 1.f / l0, i1 = 1.f / l1;

    __half* orow0 = outp + (size_t)(b*SEQ + row0) * DIM + h*DH;
    __half* orow1 = orow0 + 8*DIM;
    #pragma unroll
    for (int na = 0; na < 8; na++) {
        *(uint32_t*)&orow0[na*8 + 2*t] = pkh(o[na][0]*i0, o[na][1]*i0);
        *(uint32_t*)&orow1[na*8 + 2*t] = pkh(o[na][2]*i1, o[na][3]*i1);
    }
}

// ---------------------------------------------------------------------------
extern "C" void kernel_launch(void* const* d_in, const int* in_sizes, int n_in,
                              void* d_out, int out_size)
{
    const float* x     = (const float*)d_in[0];
    const float* W_qkv = (const float*)d_in[1];
    const float* W_out = (const float*)d_in[2];
    float*       out   = (float*)d_out;

    __half *qkvh, *attnh, *xh, *wqh, *woh;
    cudaGetSymbolAddress((void**)&qkvh,  g_qkvh);
    cudaGetSymbolAddress((void**)&attnh, g_attnh);
    cudaGetSymbolAddress((void**)&xh,    g_xh);
    cudaGetSymbolAddress((void**)&wqh,   g_wqh);
    cudaGetSymbolAddress((void**)&woh,   g_woh);

    cudaFuncSetAttribute(gemm_h16, cudaFuncAttributeMaxDynamicSharedMemorySize, G_SMEM);

    // 0) convert all inputs to fp16 (single fused kernel)
    const int na8 = MROWS*DIM/8, nb8 = QKVCOL*DIM/8, nc8 = DIM*DIM/8;
    cvt3<<<(na8 + nb8 + nc8 + 255)/256, 256>>>(x, xh, na8, W_qkv, wqh, nb8, W_out, woh, nc8);

    // 1) qkv = x @ W_qkv^T (fp16 out; Q columns pre-scaled by 1/8)
    gemm_h16<<<dim3(QKVCOL/128, MROWS/128), 256, G_SMEM>>>(xh, wqh, qkvh, nullptr,
                                                           MROWS, QKVCOL, DIM, DIM);
    // 2) causal attention (fp16 in/out)
    attn_h16<<<dim3(SEQ/128, BATCH*HEADS), 256>>>(qkvh, attnh);
    // 3) out = attn @ W_out^T (fp32 out)
    gemm_h16<<<dim3(DIM/128, MROWS/128), 256, G_SMEM>>>(attnh, woh, nullptr, out,
                                                        MROWS, DIM, DIM, 0);
}